// round 2
// baseline (speedup 1.0000x reference)
#include <cuda_runtime.h>
#include <cuda_bf16.h>

#define MARGIN 0.5f
#define EPS 1e-6f

// Global accumulator (allocation-free scratch).
__device__ double g_sum;

__global__ void init_kernel() {
    g_sum = 0.0;
}

// One warp per triplet. Lane l handles elements [4l, 4l+4) of the 128-dim rows.
__global__ void __launch_bounds__(256) triplet_kernel(
    const float* __restrict__ emb,
    const int* __restrict__ a_idx,
    const int* __restrict__ p_idx,
    const int* __restrict__ n_idx,
    int T)
{
    const int warp_in_block = threadIdx.x >> 5;
    const int lane = threadIdx.x & 31;
    const int t = blockIdx.x * 8 + warp_in_block;   // 8 warps / block

    float v = 0.0f;
    if (t < T) {
        const int ia = a_idx[t];
        const int ip = p_idx[t];
        const int in = n_idx[t];

        const float4* ra = reinterpret_cast<const float4*>(emb + (size_t)ia * 128) + lane;
        const float4* rp = reinterpret_cast<const float4*>(emb + (size_t)ip * 128) + lane;
        const float4* rn = reinterpret_cast<const float4*>(emb + (size_t)in * 128) + lane;

        // Issue all three 512B row loads before consuming (MLP=3).
        float4 va = __ldg(ra);
        float4 vp = __ldg(rp);
        float4 vn = __ldg(rn);

        float sp, sn;
        {
            float d0 = va.x - vp.x + EPS;
            float d1 = va.y - vp.y + EPS;
            float d2 = va.z - vp.z + EPS;
            float d3 = va.w - vp.w + EPS;
            sp = d0 * d0 + d1 * d1 + d2 * d2 + d3 * d3;
            float e0 = va.x - vn.x + EPS;
            float e1 = va.y - vn.y + EPS;
            float e2 = va.z - vn.z + EPS;
            float e3 = va.w - vn.w + EPS;
            sn = e0 * e0 + e1 * e1 + e2 * e2 + e3 * e3;
        }

        // Warp reduce both sums.
        #pragma unroll
        for (int off = 16; off > 0; off >>= 1) {
            sp += __shfl_down_sync(0xFFFFFFFFu, sp, off);
            sn += __shfl_down_sync(0xFFFFFFFFu, sn, off);
        }

        if (lane == 0) {
            float dpos = sqrtf(sp);
            float dneg = sqrtf(sn);
            v = fmaxf(dpos - dneg + MARGIN, 0.0f);
        }
    }

    // Block reduce: lane 0 of each warp deposits, warp 0 sums.
    __shared__ float warp_vals[8];
    if (lane == 0) warp_vals[warp_in_block] = v;
    __syncthreads();

    if (warp_in_block == 0) {
        float s = (lane < 8) ? warp_vals[lane] : 0.0f;
        #pragma unroll
        for (int off = 4; off > 0; off >>= 1)
            s += __shfl_down_sync(0xFFFFFFFFu, s, off);
        if (lane == 0)
            atomicAdd(&g_sum, (double)s);
    }
}

__global__ void finalize_kernel(float* out, int T) {
    out[0] = (float)(g_sum / (double)T);
}

extern "C" void kernel_launch(void* const* d_in, const int* in_sizes, int n_in,
                              void* d_out, int out_size) {
    const float* emb   = (const float*)d_in[0];
    // d_in[1] = labels (unused; mining is precomputed in the reference inputs)
    const int* a_idx   = (const int*)d_in[2];
    const int* p_idx   = (const int*)d_in[3];
    const int* n_idx   = (const int*)d_in[4];
    float* out         = (float*)d_out;

    const int T = in_sizes[2];

    init_kernel<<<1, 1>>>();
    const int warps_per_block = 8;
    const int blocks = (T + warps_per_block - 1) / warps_per_block;
    triplet_kernel<<<blocks, warps_per_block * 32>>>(emb, a_idx, p_idx, n_idx, T);
    finalize_kernel<<<1, 1>>>(out, T);
}

// round 4
// speedup vs baseline: 1.4518x; 1.4518x over previous
#include <cuda_runtime.h>
#include <cuda_bf16.h>

#define MARGIN 0.5f
#define EPS 1e-6f
#define WARPS_PER_BLOCK 8
#define THREADS (WARPS_PER_BLOCK * 32)

// Allocation-free scratch. Static-initialized to zero; the last finishing
// block resets them so every graph replay starts from the same state.
__device__ double g_sum = 0.0;
__device__ unsigned int g_count = 0u;

__device__ __forceinline__ float triplet_sums(const float4 va, const float4 vb)
{
    float d0 = va.x - vb.x + EPS;
    float d1 = va.y - vb.y + EPS;
    float d2 = va.z - vb.z + EPS;
    float d3 = va.w - vb.w + EPS;
    return d0 * d0 + d1 * d1 + d2 * d2 + d3 * d3;
}

__global__ void __launch_bounds__(THREADS) triplet_kernel(
    const float* __restrict__ emb,
    const int* __restrict__ a_idx,
    const int* __restrict__ p_idx,
    const int* __restrict__ n_idx,
    int T,
    float* __restrict__ out)
{
    const int warp_in_block = threadIdx.x >> 5;
    const int lane = threadIdx.x & 31;
    const int gwarp = blockIdx.x * WARPS_PER_BLOCK + warp_in_block;
    const int nwarps = gridDim.x * WARPS_PER_BLOCK;

    float acc = 0.0f;  // per-lane accumulator of relu terms (lane 0 holds them)

    // Each warp handles 2 consecutive triplets per iteration (MLP = 6 row loads).
    for (int t0 = gwarp * 2; t0 < T; t0 += nwarps * 2) {
        const int t1 = t0 + 1;
        const bool has1 = (t1 < T);

        const int ia0 = a_idx[t0];
        const int ip0 = p_idx[t0];
        const int in0 = n_idx[t0];
        const int ia1 = has1 ? a_idx[t1] : ia0;
        const int ip1 = has1 ? p_idx[t1] : ip0;
        const int in1 = has1 ? n_idx[t1] : in0;

        // Issue all six 512B row loads before consuming.
        const float4 va0 = __ldg(reinterpret_cast<const float4*>(emb + (size_t)ia0 * 128) + lane);
        const float4 vp0 = __ldg(reinterpret_cast<const float4*>(emb + (size_t)ip0 * 128) + lane);
        const float4 vn0 = __ldg(reinterpret_cast<const float4*>(emb + (size_t)in0 * 128) + lane);
        const float4 va1 = __ldg(reinterpret_cast<const float4*>(emb + (size_t)ia1 * 128) + lane);
        const float4 vp1 = __ldg(reinterpret_cast<const float4*>(emb + (size_t)ip1 * 128) + lane);
        const float4 vn1 = __ldg(reinterpret_cast<const float4*>(emb + (size_t)in1 * 128) + lane);

        float sp0 = triplet_sums(va0, vp0);
        float sn0 = triplet_sums(va0, vn0);
        float sp1 = triplet_sums(va1, vp1);
        float sn1 = triplet_sums(va1, vn1);

        #pragma unroll
        for (int off = 16; off > 0; off >>= 1) {
            sp0 += __shfl_down_sync(0xFFFFFFFFu, sp0, off);
            sn0 += __shfl_down_sync(0xFFFFFFFFu, sn0, off);
            sp1 += __shfl_down_sync(0xFFFFFFFFu, sp1, off);
            sn1 += __shfl_down_sync(0xFFFFFFFFu, sn1, off);
        }

        if (lane == 0) {
            acc += fmaxf(sqrtf(sp0) - sqrtf(sn0) + MARGIN, 0.0f);
            if (has1)
                acc += fmaxf(sqrtf(sp1) - sqrtf(sn1) + MARGIN, 0.0f);
        }
    }

    // Block reduce: lane 0 of each warp deposits its accumulator.
    __shared__ float warp_vals[WARPS_PER_BLOCK];
    if (lane == 0) warp_vals[warp_in_block] = acc;
    __syncthreads();

    if (warp_in_block == 0) {
        float s = (lane < WARPS_PER_BLOCK) ? warp_vals[lane] : 0.0f;
        #pragma unroll
        for (int off = 4; off > 0; off >>= 1)
            s += __shfl_down_sync(0xFFFFFFFFu, s, off);

        if (lane == 0) {
            atomicAdd(&g_sum, (double)s);
            __threadfence();
            unsigned int prev = atomicAdd(&g_count, 1u);
            if (prev == gridDim.x - 1) {
                // Last block: all other blocks' sums are visible.
                double total = atomicAdd(&g_sum, 0.0);  // safe read
                out[0] = (float)(total / (double)T);
                // Reset for the next graph replay.
                g_sum = 0.0;
                __threadfence();
                atomicExch(&g_count, 0u);
            }
        }
    }
}

extern "C" void kernel_launch(void* const* d_in, const int* in_sizes, int n_in,
                              void* d_out, int out_size) {
    const float* emb   = (const float*)d_in[0];
    // d_in[1] = labels (unused; mining is precomputed in the reference inputs)
    const int* a_idx   = (const int*)d_in[2];
    const int* p_idx   = (const int*)d_in[3];
    const int* n_idx   = (const int*)d_in[4];
    float* out         = (float*)d_out;

    const int T = in_sizes[2];

    // Grid-stride: 148 SMs * 16 blocks, capped by work.
    int blocks = 148 * 16;
    int max_blocks = (T + WARPS_PER_BLOCK * 2 - 1) / (WARPS_PER_BLOCK * 2);
    if (blocks > max_blocks) blocks = max_blocks;
    if (blocks < 1) blocks = 1;

    triplet_kernel<<<blocks, THREADS>>>(emb, a_idx, p_idx, n_idx, T, out);
}

// round 5
// speedup vs baseline: 1.6902x; 1.1643x over previous
#include <cuda_runtime.h>
#include <cuda_bf16.h>

#define MARGIN 0.5f
#define EPS 1e-6f
#define WARPS_PER_BLOCK 8
#define THREADS (WARPS_PER_BLOCK * 32)

// Allocation-free scratch; last finishing block resets for graph replays.
__device__ double g_sum = 0.0;
__device__ unsigned int g_count = 0u;

__device__ __forceinline__ float dsq(const float4 a, const float4 b)
{
    float d0 = a.x - b.x + EPS;
    float d1 = a.y - b.y + EPS;
    float d2 = a.z - b.z + EPS;
    float d3 = a.w - b.w + EPS;
    return fmaf(d0, d0, fmaf(d1, d1, fmaf(d2, d2, d3 * d3)));
}

// Half-warp per triplet: lanes [0,16) -> triplet h=0, lanes [16,32) -> h=1.
// Each lane loads 2 contiguous float4 (32B) per row. 4 triplets per iteration,
// all 12 row loads issued before consumption (MLP=12 per warp).
__global__ void __launch_bounds__(THREADS, 4) triplet_kernel(
    const float* __restrict__ emb,
    const int* __restrict__ a_idx,
    const int* __restrict__ p_idx,
    const int* __restrict__ n_idx,
    int T,
    float* __restrict__ out)
{
    const int lane = threadIdx.x & 31;
    const int h = lane >> 4;      // which half-warp
    const int s = lane & 15;      // sublane within half
    const int warp_in_block = threadIdx.x >> 5;
    const int gwarp = blockIdx.x * WARPS_PER_BLOCK + warp_in_block;
    const int nwarps = gridDim.x * WARPS_PER_BLOCK;

    float acc = 0.0f;

    for (int t0 = gwarp * 4; t0 < T; t0 += nwarps * 4) {
        const int tA = t0 + h;          // group A triplets: t0, t0+1
        const int tB = t0 + 2 + h;      // group B triplets: t0+2, t0+3
        const bool vA = (tA < T);
        const bool vB = (tB < T);
        const int cA = vA ? tA : 0;
        const int cB = vB ? tB : 0;

        const int iaA = a_idx[cA], ipA = p_idx[cA], inA = n_idx[cA];
        const int iaB = a_idx[cB], ipB = p_idx[cB], inB = n_idx[cB];

        const float4* raA = reinterpret_cast<const float4*>(emb + (size_t)iaA * 128) + s * 2;
        const float4* rpA = reinterpret_cast<const float4*>(emb + (size_t)ipA * 128) + s * 2;
        const float4* rnA = reinterpret_cast<const float4*>(emb + (size_t)inA * 128) + s * 2;
        const float4* raB = reinterpret_cast<const float4*>(emb + (size_t)iaB * 128) + s * 2;
        const float4* rpB = reinterpret_cast<const float4*>(emb + (size_t)ipB * 128) + s * 2;
        const float4* rnB = reinterpret_cast<const float4*>(emb + (size_t)inB * 128) + s * 2;

        // Issue all 12 loads up front.
        const float4 aA0 = __ldg(raA),     aA1 = __ldg(raA + 1);
        const float4 pA0 = __ldg(rpA),     pA1 = __ldg(rpA + 1);
        const float4 nA0 = __ldg(rnA),     nA1 = __ldg(rnA + 1);
        const float4 aB0 = __ldg(raB),     aB1 = __ldg(raB + 1);
        const float4 pB0 = __ldg(rpB),     pB1 = __ldg(rpB + 1);
        const float4 nB0 = __ldg(rnB),     nB1 = __ldg(rnB + 1);

        float spA = dsq(aA0, pA0) + dsq(aA1, pA1);
        float snA = dsq(aA0, nA0) + dsq(aA1, nA1);
        float spB = dsq(aB0, pB0) + dsq(aB1, pB1);
        float snB = dsq(aB0, nB0) + dsq(aB1, nB1);

        // Reduce within each 16-lane half (both halves in parallel).
        #pragma unroll
        for (int off = 8; off > 0; off >>= 1) {
            spA += __shfl_down_sync(0xFFFFFFFFu, spA, off, 16);
            snA += __shfl_down_sync(0xFFFFFFFFu, snA, off, 16);
            spB += __shfl_down_sync(0xFFFFFFFFu, spB, off, 16);
            snB += __shfl_down_sync(0xFFFFFFFFu, snB, off, 16);
        }

        if (s == 0) {
            if (vA) acc += fmaxf(sqrtf(spA) - sqrtf(snA) + MARGIN, 0.0f);
            if (vB) acc += fmaxf(sqrtf(spB) - sqrtf(snB) + MARGIN, 0.0f);
        }
    }

    // Full warp reduce of acc (nonzero in lanes 0 and 16).
    #pragma unroll
    for (int off = 16; off > 0; off >>= 1)
        acc += __shfl_down_sync(0xFFFFFFFFu, acc, off);

    __shared__ float warp_vals[WARPS_PER_BLOCK];
    if (lane == 0) warp_vals[warp_in_block] = acc;
    __syncthreads();

    if (warp_in_block == 0) {
        float v = (lane < WARPS_PER_BLOCK) ? warp_vals[lane] : 0.0f;
        #pragma unroll
        for (int off = 4; off > 0; off >>= 1)
            v += __shfl_down_sync(0xFFFFFFFFu, v, off);

        if (lane == 0) {
            atomicAdd(&g_sum, (double)v);
            __threadfence();
            unsigned int prev = atomicAdd(&g_count, 1u);
            if (prev == gridDim.x - 1) {
                double total = atomicAdd(&g_sum, 0.0);
                out[0] = (float)(total / (double)T);
                g_sum = 0.0;
                __threadfence();
                atomicExch(&g_count, 0u);
            }
        }
    }
}

extern "C" void kernel_launch(void* const* d_in, const int* in_sizes, int n_in,
                              void* d_out, int out_size) {
    const float* emb   = (const float*)d_in[0];
    // d_in[1] = labels (unused; mining is precomputed in the reference inputs)
    const int* a_idx   = (const int*)d_in[2];
    const int* p_idx   = (const int*)d_in[3];
    const int* n_idx   = (const int*)d_in[4];
    float* out         = (float*)d_out;

    const int T = in_sizes[2];

    // Persistent grid: 4 resident blocks per SM on 148 SMs.
    int blocks = 148 * 4;
    int max_blocks = (T + WARPS_PER_BLOCK * 4 - 1) / (WARPS_PER_BLOCK * 4);
    if (blocks > max_blocks) blocks = max_blocks;
    if (blocks < 1) blocks = 1;

    triplet_kernel<<<blocks, THREADS>>>(emb, a_idx, p_idx, n_idx, T, out);
}

// round 6
// speedup vs baseline: 1.7860x; 1.0567x over previous
#include <cuda_runtime.h>
#include <cuda_bf16.h>

#define MARGIN 0.5f
#define EPS 1e-6f
#define WARPS_PER_BLOCK 8
#define THREADS (WARPS_PER_BLOCK * 32)

// Allocation-free scratch; last finishing block resets for graph replays.
__device__ double g_sum = 0.0;
__device__ unsigned int g_count = 0u;

__device__ __forceinline__ float dsq(const float4 a, const float4 b)
{
    float d0 = a.x - b.x + EPS;
    float d1 = a.y - b.y + EPS;
    float d2 = a.z - b.z + EPS;
    float d3 = a.w - b.w + EPS;
    return fmaf(d0, d0, fmaf(d1, d1, fmaf(d2, d2, d3 * d3)));
}

// Half-warp per triplet: lanes [0,16) -> triplet h=0, lanes [16,32) -> h=1.
// Lane s loads float4 #s (bytes [16s,16s+16)) and float4 #(s+16) of each row:
// both load instructions cover dense 256B blocks (no strided half-sectors).
// 4 triplets per iteration, all 12 row loads issued before consumption.
__global__ void __launch_bounds__(THREADS, 4) triplet_kernel(
    const float* __restrict__ emb,
    const int* __restrict__ a_idx,
    const int* __restrict__ p_idx,
    const int* __restrict__ n_idx,
    int T,
    float* __restrict__ out)
{
    const int lane = threadIdx.x & 31;
    const int h = lane >> 4;      // which half-warp
    const int s = lane & 15;      // sublane within half
    const int warp_in_block = threadIdx.x >> 5;
    const int gwarp = blockIdx.x * WARPS_PER_BLOCK + warp_in_block;
    const int nwarps = gridDim.x * WARPS_PER_BLOCK;

    float acc = 0.0f;

    for (int t0 = gwarp * 4; t0 < T; t0 += nwarps * 4) {
        const int tA = t0 + h;          // group A triplets: t0, t0+1
        const int tB = t0 + 2 + h;      // group B triplets: t0+2, t0+3
        const bool vA = (tA < T);
        const bool vB = (tB < T);
        const int cA = vA ? tA : 0;
        const int cB = vB ? tB : 0;

        const int iaA = a_idx[cA], ipA = p_idx[cA], inA = n_idx[cA];
        const int iaB = a_idx[cB], ipB = p_idx[cB], inB = n_idx[cB];

        const float4* raA = reinterpret_cast<const float4*>(emb + (size_t)iaA * 128) + s;
        const float4* rpA = reinterpret_cast<const float4*>(emb + (size_t)ipA * 128) + s;
        const float4* rnA = reinterpret_cast<const float4*>(emb + (size_t)inA * 128) + s;
        const float4* raB = reinterpret_cast<const float4*>(emb + (size_t)iaB * 128) + s;
        const float4* rpB = reinterpret_cast<const float4*>(emb + (size_t)ipB * 128) + s;
        const float4* rnB = reinterpret_cast<const float4*>(emb + (size_t)inB * 128) + s;

        // Issue all 12 loads up front (each covers two dense 256B blocks).
        const float4 aA0 = __ldg(raA),     aA1 = __ldg(raA + 16);
        const float4 pA0 = __ldg(rpA),     pA1 = __ldg(rpA + 16);
        const float4 nA0 = __ldg(rnA),     nA1 = __ldg(rnA + 16);
        const float4 aB0 = __ldg(raB),     aB1 = __ldg(raB + 16);
        const float4 pB0 = __ldg(rpB),     pB1 = __ldg(rpB + 16);
        const float4 nB0 = __ldg(rnB),     nB1 = __ldg(rnB + 16);

        float spA = dsq(aA0, pA0) + dsq(aA1, pA1);
        float snA = dsq(aA0, nA0) + dsq(aA1, nA1);
        float spB = dsq(aB0, pB0) + dsq(aB1, pB1);
        float snB = dsq(aB0, nB0) + dsq(aB1, nB1);

        // Reduce within each 16-lane half (both halves in parallel).
        #pragma unroll
        for (int off = 8; off > 0; off >>= 1) {
            spA += __shfl_down_sync(0xFFFFFFFFu, spA, off, 16);
            snA += __shfl_down_sync(0xFFFFFFFFu, snA, off, 16);
            spB += __shfl_down_sync(0xFFFFFFFFu, spB, off, 16);
            snB += __shfl_down_sync(0xFFFFFFFFu, snB, off, 16);
        }

        if (s == 0) {
            if (vA) acc += fmaxf(sqrtf(spA) - sqrtf(snA) + MARGIN, 0.0f);
            if (vB) acc += fmaxf(sqrtf(spB) - sqrtf(snB) + MARGIN, 0.0f);
        }
    }

    // Full warp reduce of acc (nonzero in lanes 0 and 16).
    #pragma unroll
    for (int off = 16; off > 0; off >>= 1)
        acc += __shfl_down_sync(0xFFFFFFFFu, acc, off);

    __shared__ float warp_vals[WARPS_PER_BLOCK];
    if (lane == 0) warp_vals[warp_in_block] = acc;
    __syncthreads();

    if (warp_in_block == 0) {
        float v = (lane < WARPS_PER_BLOCK) ? warp_vals[lane] : 0.0f;
        #pragma unroll
        for (int off = 4; off > 0; off >>= 1)
            v += __shfl_down_sync(0xFFFFFFFFu, v, off);

        if (lane == 0) {
            atomicAdd(&g_sum, (double)v);
            __threadfence();
            unsigned int prev = atomicAdd(&g_count, 1u);
            if (prev == gridDim.x - 1) {
                double total = atomicAdd(&g_sum, 0.0);
                out[0] = (float)(total / (double)T);
                g_sum = 0.0;
                __threadfence();
                atomicExch(&g_count, 0u);
            }
        }
    }
}

extern "C" void kernel_launch(void* const* d_in, const int* in_sizes, int n_in,
                              void* d_out, int out_size) {
    const float* emb   = (const float*)d_in[0];
    // d_in[1] = labels (unused; mining is precomputed in the reference inputs)
    const int* a_idx   = (const int*)d_in[2];
    const int* p_idx   = (const int*)d_in[3];
    const int* n_idx   = (const int*)d_in[4];
    float* out         = (float*)d_out;

    const int T = in_sizes[2];

    // Persistent grid: 4 resident blocks per SM on 148 SMs.
    int blocks = 148 * 4;
    int max_blocks = (T + WARPS_PER_BLOCK * 4 - 1) / (WARPS_PER_BLOCK * 4);
    if (blocks > max_blocks) blocks = max_blocks;
    if (blocks < 1) blocks = 1;

    triplet_kernel<<<blocks, THREADS>>>(emb, a_idx, p_idx, n_idx, T, out);
}